// round 6
// baseline (speedup 1.0000x reference)
#include <cuda_runtime.h>

// Kaldi LinearResample 16000 -> 14400, LPF_WIDTH=6 (polyphase, up=9, stride=10).
//   out[b, 9k+i] = sum_m w[i][m] * x[b, 10k + fi[i] + m],  x zero-padded outside [0,T)
//   fi[i] = {-6,-5,-4,-3,-2,-1,0,2,3};  tap weight depends only on n = 9*(fi[i]+m) - 10*i.
//   All 121 nonzero taps baked as compile-time float literals -> FFMA-imm.

#define T_IN        480000
#define TOT_K       48000
#define UP          9
#define TOT_OUT     (TOT_K * UP)
#define TILE_K      320
#define NTHREADS    320
#define TILE_F      3216          // 10*319 + 22 + shift(<=2), float4 multiple
#define TILES_PER_ROW 150         // 48000 / 320 exactly -> every tile full
#define NCTA        888           // 148 SM * 6 CTAs, persistent

// ---------------- compile-time weight table ----------------
constexpr double KPI = 3.14159265358979323846264338327950288;

constexpr double tsin(double x) {
    while (x >  KPI) x -= 2.0 * KPI;
    while (x < -KPI) x += 2.0 * KPI;
    double x2 = x * x, term = x, s = x;
    for (int k = 1; k <= 16; ++k) {
        term *= -x2 / (double)((2 * k) * (2 * k + 1));
        s += term;
    }
    return s;
}
constexpr double tcos(double x) { return tsin(KPI * 0.5 - x); }

struct WTab { float w[9][14]; };
constexpr WTab make_wtab() {
    WTab t{};
    constexpr int FI[9] = {-6, -5, -4, -3, -2, -1, 0, 2, 3};
    for (int i = 0; i < 9; ++i)
        for (int m = 0; m < 14; ++m) {
            int n = 9 * (FI[i] + m) - 10 * i;
            int an = n < 0 ? -n : n;
            double v = 0.0;
            if (an == 0)      v = 0.891;            // 2*lowpass_cutoff/orig_freq
            else if (an <= 60)
                v = (1.0 + tcos(0.0165 * KPI * an)) * tsin(0.099 * KPI * an)
                    * 9.0 / (2.0 * KPI * an);
            t.w[i][m] = (float)v;
        }
    return t;
}
__device__ constexpr WTab WT = make_wtab();

// ---------------- cp.async helpers ----------------
__device__ __forceinline__ void cp_async16(float* smem_dst, const float* gsrc) {
    unsigned saddr = (unsigned)__cvta_generic_to_shared(smem_dst);
    asm volatile("cp.async.cg.shared.global [%0], [%1], 16;" :: "r"(saddr), "l"(gsrc));
}
#define CP_COMMIT() asm volatile("cp.async.commit_group;" ::: "memory")
#define CP_WAIT1()  asm volatile("cp.async.wait_group 1;"  ::: "memory")

// ---------------- staging (one tile into one smem buffer) ----------------
__device__ __forceinline__ void stage_tile(float* xs, const float* __restrict__ in,
                                           int t) {
    const int b  = t / TILES_PER_ROW;
    const int kt = (t - b * TILES_PER_ROW) * TILE_K;
    const float* rowin = in + (size_t)b * T_IN;
    const int gstart = 10 * kt - 6;
    const int g4 = gstart & ~3;

    if (g4 >= 0 && g4 + TILE_F <= T_IN) {
        // interior (148 of 150 tiles per row): pure async 16B copies
        for (int v = threadIdx.x; v < TILE_F / 4; v += NTHREADS)
            cp_async16(xs + 4 * v, rowin + g4 + 4 * v);
    } else {
        // edge tile: guarded scalar path with zero padding
        for (int v = threadIdx.x; v < TILE_F / 4; v += NTHREADS) {
            int g = g4 + 4 * v;
            float4 val;
            if (g >= 0 && g <= T_IN - 4) {
                val = *reinterpret_cast<const float4*>(rowin + g);
            } else {
                val.x = (g + 0 >= 0 && g + 0 < T_IN) ? rowin[g + 0] : 0.0f;
                val.y = (g + 1 >= 0 && g + 1 < T_IN) ? rowin[g + 1] : 0.0f;
                val.z = (g + 2 >= 0 && g + 2 < T_IN) ? rowin[g + 2] : 0.0f;
                val.w = (g + 3 >= 0 && g + 3 < T_IN) ? rowin[g + 3] : 0.0f;
            }
            *reinterpret_cast<float4*>(xs + 4 * v) = val;
        }
    }
}

__global__ __launch_bounds__(NTHREADS, 6)
void sp_resample_kernel(const float* __restrict__ in, float* __restrict__ out,
                        int ntiles) {
    __shared__ float xs[2][TILE_F];
    __shared__ float os[TILE_K * UP];      // warp-private 288-float blocks

    const int tid  = threadIdx.x;
    const int wid  = tid >> 5;
    const int lane = tid & 31;
    const int stride = gridDim.x;

    int t0 = blockIdx.x;
    if (t0 < ntiles) stage_tile(xs[0], in, t0);
    CP_COMMIT();

    int cur = 0;
    for (int t = t0; t < ntiles; t += stride) {
        __syncthreads();                       // prev compute done reading xs[1-cur]
        int tn = t + stride;
        if (tn < ntiles) stage_tile(xs[1 - cur], in, tn);
        CP_COMMIT();
        CP_WAIT1();                            // xs[cur]'s cp.async group complete
        __syncthreads();                       // data visible to all warps

        const int b  = t / TILES_PER_ROW;
        const int kt = (t - b * TILES_PER_ROW) * TILE_K;
        const int gstart = 10 * kt - 6;
        const int shift  = gstart & 3;                 // 0 or 2 (gstart even)
        const float* xb = xs[cur];

        {
            float2 xr2[11];
            const int w0 = 10 * tid + shift;           // even -> aligned float2
#pragma unroll
            for (int c = 0; c < 11; ++c)
                xr2[c] = *reinterpret_cast<const float2*>(xb + w0 + 2 * c);
#define XR(c) (((c) & 1) ? xr2[(c) >> 1].y : xr2[(c) >> 1].x)

            constexpr int FI6[9] = {0, 1, 2, 3, 4, 5, 6, 8, 9};
            constexpr int N0[9]  = {-54, -55, -56, -57, -58, -59, -60, -52, -53};
#pragma unroll
            for (int i = 0; i < 9; ++i) {
                float acc = 0.0f;
#pragma unroll
                for (int m = 0; m < 14; ++m) {
                    const int n  = N0[i] + 9 * m;
                    const int an = (n < 0) ? -n : n;
                    if (an <= 60) {                    // pruned at compile time
                        acc = fmaf(WT.w[i][m], XR(FI6[i] + m), acc);
                    }
                }
                os[9 * tid + i] = acc;
            }
#undef XR
        }
        __syncwarp();

        {
            const size_t ob = (size_t)b * TOT_OUT + (size_t)9 * (kt + 32 * wid);
            const float4* src = reinterpret_cast<const float4*>(os + 288 * wid);
            float4* dst = reinterpret_cast<float4*>(out + ob);
#pragma unroll
            for (int v = lane; v < 72; v += 32)        // 288 floats = 72 float4
                dst[v] = src[v];
        }
        cur ^= 1;
    }
}

extern "C" void kernel_launch(void* const* d_in, const int* in_sizes, int n_in,
                              void* d_out, int out_size) {
    const float* in = (const float*)d_in[0];
    float* out = (float*)d_out;
    const int B = in_sizes[0] / T_IN;
    const int ntiles = B * TILES_PER_ROW;
    sp_resample_kernel<<<NCTA, NTHREADS>>>(in, out, ntiles);
}

// round 7
// speedup vs baseline: 1.0044x; 1.0044x over previous
#include <cuda_runtime.h>

// Kaldi LinearResample 16000 -> 14400, LPF_WIDTH=6 (polyphase, up=9, stride=10).
//   out[b, 9k+i] = sum_m w[i][m] * x[b, 10k + fi[i] + m],  x zero-padded outside [0,T)
//   fi[i] = {-6,-5,-4,-3,-2,-1,0,2,3};  tap weight depends only on n = 9*(fi[i]+m) - 10*i.
//   All 121 nonzero taps baked as compile-time float literals -> FFMA-imm.

#define T_IN        480000
#define TOT_K       48000
#define UP          9
#define TOT_OUT     (TOT_K * UP)
#define TILE_K      320
#define NTHREADS    320
#define TILE_F      3216          // 10*319 + 22 + shift(<=2), float4 multiple
#define TILES_PER_ROW 150         // 48000 / 320 exactly -> every tile full
#define NSTAGE      3
#define NCTA        592           // 148 SM * 4 CTAs, persistent

// ---------------- compile-time weight table ----------------
constexpr double KPI = 3.14159265358979323846264338327950288;

constexpr double tsin(double x) {
    while (x >  KPI) x -= 2.0 * KPI;
    while (x < -KPI) x += 2.0 * KPI;
    double x2 = x * x, term = x, s = x;
    for (int k = 1; k <= 16; ++k) {
        term *= -x2 / (double)((2 * k) * (2 * k + 1));
        s += term;
    }
    return s;
}
constexpr double tcos(double x) { return tsin(KPI * 0.5 - x); }

struct WTab { float w[9][14]; };
constexpr WTab make_wtab() {
    WTab t{};
    constexpr int FI[9] = {-6, -5, -4, -3, -2, -1, 0, 2, 3};
    for (int i = 0; i < 9; ++i)
        for (int m = 0; m < 14; ++m) {
            int n = 9 * (FI[i] + m) - 10 * i;
            int an = n < 0 ? -n : n;
            double v = 0.0;
            if (an == 0)      v = 0.891;            // 2*lowpass_cutoff/orig_freq
            else if (an <= 60)
                v = (1.0 + tcos(0.0165 * KPI * an)) * tsin(0.099 * KPI * an)
                    * 9.0 / (2.0 * KPI * an);
            t.w[i][m] = (float)v;
        }
    return t;
}
__device__ constexpr WTab WT = make_wtab();

// ---------------- cp.async helpers ----------------
__device__ __forceinline__ void cp_async16(float* smem_dst, const float* gsrc) {
    unsigned saddr = (unsigned)__cvta_generic_to_shared(smem_dst);
    asm volatile("cp.async.cg.shared.global [%0], [%1], 16;" :: "r"(saddr), "l"(gsrc));
}
#define CP_COMMIT() asm volatile("cp.async.commit_group;" ::: "memory")
#define CP_WAIT2()  asm volatile("cp.async.wait_group 2;"  ::: "memory")

// streaming store: evict-first, output is never re-read
__device__ __forceinline__ void stg_cs16(float4* dst, float4 v) {
    asm volatile("st.global.cs.v4.f32 [%0], {%1, %2, %3, %4};"
                 :: "l"(dst), "f"(v.x), "f"(v.y), "f"(v.z), "f"(v.w) : "memory");
}

// ---------------- staging (one tile into one smem buffer) ----------------
__device__ __forceinline__ void stage_tile(float* xs, const float* __restrict__ in,
                                           int t) {
    const int b  = t / TILES_PER_ROW;
    const int kt = (t - b * TILES_PER_ROW) * TILE_K;
    const float* rowin = in + (size_t)b * T_IN;
    const int gstart = 10 * kt - 6;
    const int g4 = gstart & ~3;

    if (g4 >= 0 && g4 + TILE_F <= T_IN) {
        // interior (148 of 150 tiles per row): pure async 16B copies
        for (int v = threadIdx.x; v < TILE_F / 4; v += NTHREADS)
            cp_async16(xs + 4 * v, rowin + g4 + 4 * v);
    } else {
        // edge tile: guarded scalar path with zero padding
        for (int v = threadIdx.x; v < TILE_F / 4; v += NTHREADS) {
            int g = g4 + 4 * v;
            float4 val;
            if (g >= 0 && g <= T_IN - 4) {
                val = *reinterpret_cast<const float4*>(rowin + g);
            } else {
                val.x = (g + 0 >= 0 && g + 0 < T_IN) ? rowin[g + 0] : 0.0f;
                val.y = (g + 1 >= 0 && g + 1 < T_IN) ? rowin[g + 1] : 0.0f;
                val.z = (g + 2 >= 0 && g + 2 < T_IN) ? rowin[g + 2] : 0.0f;
                val.w = (g + 3 >= 0 && g + 3 < T_IN) ? rowin[g + 3] : 0.0f;
            }
            *reinterpret_cast<float4*>(xs + 4 * v) = val;
        }
    }
}

__global__ __launch_bounds__(NTHREADS, 4)
void sp_resample_kernel(const float* __restrict__ in, float* __restrict__ out,
                        int ntiles) {
    __shared__ float xs[NSTAGE][TILE_F];
    __shared__ float os[TILE_K * UP];      // warp-private 288-float blocks

    const int tid  = threadIdx.x;
    const int wid  = tid >> 5;
    const int lane = tid & 31;
    const int stride = gridDim.x;

    const int t0 = blockIdx.x;
    // prefill stages 0 and 1
    if (t0 < ntiles) stage_tile(xs[0], in, t0);
    CP_COMMIT();
    if (t0 + stride < ntiles) stage_tile(xs[1], in, t0 + stride);
    CP_COMMIT();

    int cur = 0;
    for (int t = t0; t < ntiles; t += stride) {
        __syncthreads();                       // stage (cur+2)%3 free of readers
        int tn = t + 2 * stride;
        if (tn < ntiles) stage_tile(xs[(cur + 2) % NSTAGE], in, tn);
        CP_COMMIT();
        CP_WAIT2();                            // xs[cur] complete (2 groups younger)
        __syncthreads();                       // data visible to all warps

        const int b  = t / TILES_PER_ROW;
        const int kt = (t - b * TILES_PER_ROW) * TILE_K;
        const int gstart = 10 * kt - 6;
        const int shift  = gstart & 3;                 // 0 or 2 (gstart even)
        const float* xb = xs[cur];

        {
            float2 xr2[11];
            const int w0 = 10 * tid + shift;           // even -> aligned float2
#pragma unroll
            for (int c = 0; c < 11; ++c)
                xr2[c] = *reinterpret_cast<const float2*>(xb + w0 + 2 * c);
#define XR(c) (((c) & 1) ? xr2[(c) >> 1].y : xr2[(c) >> 1].x)

            constexpr int FI6[9] = {0, 1, 2, 3, 4, 5, 6, 8, 9};
            constexpr int N0[9]  = {-54, -55, -56, -57, -58, -59, -60, -52, -53};
#pragma unroll
            for (int i = 0; i < 9; ++i) {
                float acc = 0.0f;
#pragma unroll
                for (int m = 0; m < 14; ++m) {
                    const int n  = N0[i] + 9 * m;
                    const int an = (n < 0) ? -n : n;
                    if (an <= 60) {                    // pruned at compile time
                        acc = fmaf(WT.w[i][m], XR(FI6[i] + m), acc);
                    }
                }
                os[9 * tid + i] = acc;
            }
#undef XR
        }
        __syncwarp();

        {
            const size_t ob = (size_t)b * TOT_OUT + (size_t)9 * (kt + 32 * wid);
            const float4* src = reinterpret_cast<const float4*>(os + 288 * wid);
            float4* dst = reinterpret_cast<float4*>(out + ob);
#pragma unroll
            for (int v = lane; v < 72; v += 32)        // 288 floats = 72 float4
                stg_cs16(dst + v, src[v]);
        }
        cur = (cur + 1) % NSTAGE;
    }
}

extern "C" void kernel_launch(void* const* d_in, const int* in_sizes, int n_in,
                              void* d_out, int out_size) {
    const float* in = (const float*)d_in[0];
    float* out = (float*)d_out;
    const int B = in_sizes[0] / T_IN;
    const int ntiles = B * TILES_PER_ROW;
    sp_resample_kernel<<<NCTA, NTHREADS>>>(in, out, ntiles);
}